// round 15
// baseline (speedup 1.0000x reference)
#include <cuda_runtime.h>
#include <cuda_fp16.h>
#include <cstdint>

#define N_NODES   50000
#define N_EDGES   800000
#define N_FEAT    128
#define N_CLASSES 64

#define SCAN_BLK  1024
#define SCAN_NB   ((N_NODES + SCAN_BLK - 1) / SCAN_BLK)   // 49

#define LIN_TM    128                                     // nodes per k_lin block
#define LIN_KC    64                                      // k-chunk width
#define LIN_PADC  68                                      // padded chunk row (floats)
#define LIN_SMEM  ((LIN_TM + N_CLASSES) * LIN_PADC * 4)   // 52224 B dynamic smem

// -------- device scratch (no cudaMalloc allowed) --------
__device__ int    g_is64;
__device__ int    g_cnt[N_NODES];
__device__ int    g_fill[N_NODES];
__device__ int    g_rowstart[N_NODES];
__device__ float  g_dinv[N_NODES];
__device__ int    g_col[N_EDGES];
__device__ int    g_part[SCAN_NB];
__device__ __align__(16) __half g_y [(size_t)N_NODES * N_CLASSES];  // fp16 rows
__device__ __align__(16) __half g_h1[(size_t)N_NODES * N_CLASSES];  // fp16 rows

// ---------------------------------------------------------------------------
// 1) init: zero counters; warp 0 of block 0 detects edge dtype via ballot.
// ---------------------------------------------------------------------------
__global__ void k_init(const int* __restrict__ ebuf, int n) {
    int i = blockIdx.x * blockDim.x + threadIdx.x;
    if (i < n) g_cnt[i] = 0;
    if (blockIdx.x == 0 && threadIdx.x < 32) {
        int nz = (ebuf[2 * threadIdx.x + 1] != 0) ? 1 : 0;
        unsigned ball = __ballot_sync(0xffffffffu, nz);
        if (threadIdx.x == 0) g_is64 = (ball == 0) ? 1 : 0;
    }
}

// 2) histogram of dst, decoding raw buffer directly
__global__ void k_count(const int* __restrict__ buf, int E, int N) {
    int e = blockIdx.x * blockDim.x + threadIdx.x;
    if (e >= E) return;
    int d = g_is64 ? buf[2 * E + 2 * e] : buf[E + e];
    if ((unsigned)d >= (unsigned)N) d = 0;
    atomicAdd(&g_cnt[d], 1);
}

// 3) per-block sums for the scan
__global__ void k_scan_partials(int n) {
    __shared__ int wsum[32];
    int idx  = blockIdx.x * SCAN_BLK + threadIdx.x;
    int lane = threadIdx.x & 31;
    int wid  = threadIdx.x >> 5;
    int v = (idx < n) ? g_cnt[idx] : 0;
    #pragma unroll
    for (int o = 16; o; o >>= 1) v += __shfl_xor_sync(0xffffffffu, v, o);
    if (lane == 0) wsum[wid] = v;
    __syncthreads();
    if (wid == 0) {
        int t = wsum[lane];
        #pragma unroll
        for (int o = 16; o; o >>= 1) t += __shfl_xor_sync(0xffffffffu, t, o);
        if (lane == 0) g_part[blockIdx.x] = t;
    }
}

// ---------------------------------------------------------------------------
// 4) y = x @ W^T — tiled GEMM (side stream, overlapped with CSR build).
//    fp32 accumulate; store fp16 rows.
// ---------------------------------------------------------------------------
__global__ __launch_bounds__(256, 3)
void k_lin(const float* __restrict__ x, const float* __restrict__ W, int n) {
    extern __shared__ float sm[];
    float* ws = sm;                               // [N_CLASSES][LIN_PADC]
    float* xs = sm + N_CLASSES * LIN_PADC;        // [LIN_TM][LIN_PADC]

    const int t     = threadIdx.x;
    const int node0 = blockIdx.x * LIN_TM;
    const int tx    = t & 15;                     // classes tx + 16j
    const int ty    = t >> 4;                     // nodes 8*ty + i

    float acc[8][4] = {};

    #pragma unroll
    for (int c = 0; c < N_FEAT / LIN_KC; c++) {
        const int k0 = c * LIN_KC;

        for (int f = t; f < N_CLASSES * 16; f += 256) {
            int row = f >> 4, c4 = (f & 15) << 2;
            float4 v = reinterpret_cast<const float4*>(W + (size_t)row * N_FEAT + k0 + c4)[0];
            reinterpret_cast<float4*>(ws + row * LIN_PADC + c4)[0] = v;
        }
        for (int f = t; f < LIN_TM * 16; f += 256) {
            int row = f >> 4, c4 = (f & 15) << 2;
            int node = node0 + row;
            float4 v = (node < n)
                ? reinterpret_cast<const float4*>(x + (size_t)node * N_FEAT + k0 + c4)[0]
                : make_float4(0.f, 0.f, 0.f, 0.f);
            reinterpret_cast<float4*>(xs + row * LIN_PADC + c4)[0] = v;
        }
        __syncthreads();

        const float* xb = xs + (8 * ty) * LIN_PADC;
        #pragma unroll
        for (int k4 = 0; k4 < LIN_KC / 4; k4++) {
            float4 b[4];
            #pragma unroll
            for (int j = 0; j < 4; j++)
                b[j] = reinterpret_cast<const float4*>(ws + (tx + 16 * j) * LIN_PADC)[k4];
            #pragma unroll
            for (int i = 0; i < 8; i++) {
                float4 a = reinterpret_cast<const float4*>(xb + i * LIN_PADC)[k4];
                #pragma unroll
                for (int j = 0; j < 4; j++) {
                    acc[i][j] = fmaf(a.x, b[j].x, acc[i][j]);
                    acc[i][j] = fmaf(a.y, b[j].y, acc[i][j]);
                    acc[i][j] = fmaf(a.z, b[j].z, acc[i][j]);
                    acc[i][j] = fmaf(a.w, b[j].w, acc[i][j]);
                }
            }
        }
        __syncthreads();
    }

    #pragma unroll
    for (int i = 0; i < 8; i++) {
        int node = node0 + 8 * ty + i;
        if (node < n) {
            __half* o = g_y + (size_t)node * N_CLASSES + tx;
            o[0]  = __float2half_rn(acc[i][0]);
            o[16] = __float2half_rn(acc[i][1]);
            o[32] = __float2half_rn(acc[i][2]);
            o[48] = __float2half_rn(acc[i][3]);
        }
    }
}

// 5) scan apply (tops inlined): rowstart, fill cursor, dinv
__global__ void k_scan_apply(int n) {
    __shared__ int wsum[32];
    __shared__ int sexcl[SCAN_NB];
    const int lane = threadIdx.x & 31;
    const int wid  = threadIdx.x >> 5;

    if (wid == 0) {
        int i0 = 2 * lane, i1 = 2 * lane + 1;
        int a = (i0 < SCAN_NB) ? g_part[i0] : 0;
        int b = (i1 < SCAN_NB) ? g_part[i1] : 0;
        int pair = a + b, incl = pair;
        #pragma unroll
        for (int o = 1; o < 32; o <<= 1) {
            int tt = __shfl_up_sync(0xffffffffu, incl, o);
            if (lane >= o) incl += tt;
        }
        int excl = incl - pair;
        if (i0 < SCAN_NB) sexcl[i0] = excl;
        if (i1 < SCAN_NB) sexcl[i1] = excl + a;
    }
    __syncthreads();
    const int block_off = sexcl[blockIdx.x];

    int idx = blockIdx.x * SCAN_BLK + threadIdx.x;
    int v = (idx < n) ? g_cnt[idx] : 0;

    int incl = v;
    #pragma unroll
    for (int o = 1; o < 32; o <<= 1) {
        int t = __shfl_up_sync(0xffffffffu, incl, o);
        if (lane >= o) incl += t;
    }
    if (lane == 31) wsum[wid] = incl;
    __syncthreads();
    if (wid == 0) {
        int w = wsum[lane];
        int wi = w;
        #pragma unroll
        for (int o = 1; o < 32; o <<= 1) {
            int t = __shfl_up_sync(0xffffffffu, wi, o);
            if (lane >= o) wi += t;
        }
        wsum[lane] = wi - w;
    }
    __syncthreads();

    if (idx < n) {
        int excl = block_off + wsum[wid] + incl - v;
        g_rowstart[idx] = excl;
        g_fill[idx]     = excl;
        g_dinv[idx]     = rsqrtf((float)(v + 1));
    }
}

// 6) fill CSR columns, decoding raw buffer directly
__global__ void k_fill(const int* __restrict__ buf, int E, int N) {
    int e = blockIdx.x * blockDim.x + threadIdx.x;
    if (e >= E) return;
    int s, d;
    if (g_is64) { s = buf[2 * e];  d = buf[2 * E + 2 * e]; }
    else        { s = buf[e];      d = buf[E + e]; }
    if ((unsigned)s >= (unsigned)N) s = 0;
    if ((unsigned)d >= (unsigned)N) d = 0;
    int pos = atomicAdd(&g_fill[d], 1);
    g_col[pos] = s;
}

// ---------------------------------------------------------------------------
// Hop core: warp per node, lane owns one half2 (64 feats). fp32 accumulate.
// Each edge-row read = one 128B cache line per warp.
// ---------------------------------------------------------------------------
__device__ __forceinline__ float2 hop_accum(const __half* __restrict__ yin,
                                            int i, int lane) {
    const float di = g_dinv[i];
    const int   rs = g_rowstart[i];
    const int   re = rs + g_cnt[i];

    float ax = 0.0f, ay = 0.0f;
    int e = rs;
    for (; e + 8 <= re; e += 8) {
        int    j[8];
        float  w[8];
        __half2 h[8];
        #pragma unroll
        for (int q = 0; q < 8; q++) j[q] = g_col[e + q];
        #pragma unroll
        for (int q = 0; q < 8; q++) w[q] = g_dinv[j[q]];
        #pragma unroll
        for (int q = 0; q < 8; q++)
            h[q] = reinterpret_cast<const __half2*>(yin + (size_t)j[q] * N_CLASSES)[lane];
        #pragma unroll
        for (int q = 0; q < 8; q++) {
            float2 v = __half22float2(h[q]);
            ax = fmaf(w[q], v.x, ax);
            ay = fmaf(w[q], v.y, ay);
        }
    }
    for (; e < re; e++) {
        int jj = g_col[e];
        float w = g_dinv[jj];
        float2 v = __half22float2(
            reinterpret_cast<const __half2*>(yin + (size_t)jj * N_CLASSES)[lane]);
        ax = fmaf(w, v.x, ax); ay = fmaf(w, v.y, ay);
    }

    float2 self = __half22float2(
        reinterpret_cast<const __half2*>(yin + (size_t)i * N_CLASSES)[lane]);
    float2 o;
    o.x = fmaf(di, ax, di * di * self.x);
    o.y = fmaf(di, ay, di * di * self.y);
    return o;
}

// 7) hop 1: y -> h1 (fp16 rows out)
__global__ void k_hop1() {
    int warp = (blockIdx.x * blockDim.x + threadIdx.x) >> 5;
    int lane = threadIdx.x & 31;
    if (warp >= N_NODES) return;
    float2 o = hop_accum(g_y, warp, lane);
    reinterpret_cast<__half2*>(g_h1 + (size_t)warp * N_CLASSES)[lane] =
        __floats2half2_rn(o.x, o.y);
}

// 8) hop 2 fused with bias + log_softmax (fp32 out)
__global__ void k_hop2_head(const float* __restrict__ b, float* __restrict__ out) {
    int warp = (blockIdx.x * blockDim.x + threadIdx.x) >> 5;
    int lane = threadIdx.x & 31;
    if (warp >= N_NODES) return;

    float2 o  = hop_accum(g_h1, warp, lane);
    float2 bb = reinterpret_cast<const float2*>(b)[lane];
    o.x += bb.x;
    o.y += bb.y;

    float m = fmaxf(o.x, o.y);
    #pragma unroll
    for (int s = 16; s; s >>= 1) m = fmaxf(m, __shfl_xor_sync(0xffffffffu, m, s));

    float ssum = __expf(o.x - m) + __expf(o.y - m);
    #pragma unroll
    for (int s = 16; s; s >>= 1) ssum += __shfl_xor_sync(0xffffffffu, ssum, s);

    float ls = m + __logf(ssum);
    float2 r;
    r.x = o.x - ls;
    r.y = o.y - ls;
    reinterpret_cast<float2*>(out + (size_t)warp * N_CLASSES)[lane] = r;
}

// ---------------------------------------------------------------------------
// launch: edge chain on capture stream; k_lin forked onto a side stream.
// ---------------------------------------------------------------------------
extern "C" void kernel_launch(void* const* d_in, const int* in_sizes, int n_in,
                              void* d_out, int out_size) {
    int ix = 0, ie = 1, iw = 2, ib = 3;
    for (int k = 0; k < n_in && k < 4; k++) {
        if      (in_sizes[k] == N_NODES * N_FEAT)   ix = k;
        else if (in_sizes[k] == 2 * N_EDGES)        ie = k;
        else if (in_sizes[k] == N_CLASSES * N_FEAT) iw = k;
        else if (in_sizes[k] == N_CLASSES)          ib = k;
    }
    const float* x    = (const float*)d_in[ix];
    const int*   ebuf = (const int*)d_in[ie];
    const float* W    = (const float*)d_in[iw];
    const float* b    = (const float*)d_in[ib];
    float* out = (float*)d_out;

    const int N = N_NODES;
    const int E = N_EDGES;

    static int inited = 0;
    static cudaStream_t s1;
    static cudaEvent_t ev_fork, ev_join;
    if (!inited) {
        cudaFuncSetAttribute(k_lin, cudaFuncAttributeMaxDynamicSharedMemorySize, LIN_SMEM);
        cudaStreamCreateWithFlags(&s1, cudaStreamNonBlocking);
        cudaEventCreateWithFlags(&ev_fork, cudaEventDisableTiming);
        cudaEventCreateWithFlags(&ev_join, cudaEventDisableTiming);
        inited = 1;
    }

    // fork: side stream runs the GEMM concurrently with the CSR build
    cudaEventRecord(ev_fork, 0);
    cudaStreamWaitEvent(s1, ev_fork, 0);
    k_lin<<<(N + LIN_TM - 1) / LIN_TM, 256, LIN_SMEM, s1>>>(x, W, N);
    cudaEventRecord(ev_join, s1);

    // edge chain on the capture stream
    k_init         <<<(N + 255) / 256, 256>>>(ebuf, N);
    k_count        <<<(E + 255) / 256, 256>>>(ebuf, E, N);
    k_scan_partials<<<SCAN_NB, SCAN_BLK>>>(N);
    k_scan_apply   <<<SCAN_NB, SCAN_BLK>>>(N);
    k_fill         <<<(E + 255) / 256, 256>>>(ebuf, E, N);

    // join: hops need both the CSR and y
    cudaStreamWaitEvent(0, ev_join, 0);

    const long long hop_threads = (long long)N * 32;
    const int hop_blocks = (int)((hop_threads + 255) / 256);
    k_hop1     <<<hop_blocks, 256>>>();
    k_hop2_head<<<hop_blocks, 256>>>(b, out);
}

// round 17
// speedup vs baseline: 1.0666x; 1.0666x over previous
#include <cuda_runtime.h>
#include <cuda_fp16.h>
#include <cstdint>

#define N_NODES   50000
#define N_EDGES   800000
#define N_FEAT    128
#define N_CLASSES 64

#define SCAN_BLK  1024
#define SCAN_NB   ((N_NODES + SCAN_BLK - 1) / SCAN_BLK)   // 49

#define LIN_TM    128
#define LIN_KC    64
#define LIN_PADC  68
#define LIN_SMEM  ((LIN_TM + N_CLASSES) * LIN_PADC * 4)   // 52224 B

// -------- device scratch --------
__device__ int    g_is64;
__device__ int    g_cnt[N_NODES];
__device__ int    g_fill[N_NODES];
__device__ int    g_rowstart[N_NODES];
__device__ float  g_dinv[N_NODES];
__device__ int    g_col[N_EDGES];
__device__ int    g_part[SCAN_NB];
__device__ __align__(16) __half g_y [(size_t)N_NODES * N_CLASSES];  // y, then ys = dinv*y
__device__ __align__(16) __half g_h1[(size_t)N_NODES * N_CLASSES];  // h1s = di^2*(sum+self)

// ---------------------------------------------------------------------------
// 1) init: zero counters; dtype detect via ballot
// ---------------------------------------------------------------------------
__global__ void k_init(const int* __restrict__ ebuf, int n) {
    int i = blockIdx.x * blockDim.x + threadIdx.x;
    if (i < n) g_cnt[i] = 0;
    if (blockIdx.x == 0 && threadIdx.x < 32) {
        int nz = (ebuf[2 * threadIdx.x + 1] != 0) ? 1 : 0;
        unsigned ball = __ballot_sync(0xffffffffu, nz);
        if (threadIdx.x == 0) g_is64 = (ball == 0) ? 1 : 0;
    }
}

// 2) histogram of dst
__global__ void k_count(const int* __restrict__ buf, int E, int N) {
    int e = blockIdx.x * blockDim.x + threadIdx.x;
    if (e >= E) return;
    int d = g_is64 ? buf[2 * E + 2 * e] : buf[E + e];
    if ((unsigned)d >= (unsigned)N) d = 0;
    atomicAdd(&g_cnt[d], 1);
}

// 3) per-block sums
__global__ void k_scan_partials(int n) {
    __shared__ int wsum[32];
    int idx  = blockIdx.x * SCAN_BLK + threadIdx.x;
    int lane = threadIdx.x & 31;
    int wid  = threadIdx.x >> 5;
    int v = (idx < n) ? g_cnt[idx] : 0;
    #pragma unroll
    for (int o = 16; o; o >>= 1) v += __shfl_xor_sync(0xffffffffu, v, o);
    if (lane == 0) wsum[wid] = v;
    __syncthreads();
    if (wid == 0) {
        int t = wsum[lane];
        #pragma unroll
        for (int o = 16; o; o >>= 1) t += __shfl_xor_sync(0xffffffffu, t, o);
        if (lane == 0) g_part[blockIdx.x] = t;
    }
}

// ---------------------------------------------------------------------------
// 4) y = x @ W^T — tiled GEMM (side stream). fp32 accumulate, fp16 store.
// ---------------------------------------------------------------------------
__global__ __launch_bounds__(256, 3)
void k_lin(const float* __restrict__ x, const float* __restrict__ W, int n) {
    extern __shared__ float sm[];
    float* ws = sm;
    float* xs = sm + N_CLASSES * LIN_PADC;

    const int t     = threadIdx.x;
    const int node0 = blockIdx.x * LIN_TM;
    const int tx    = t & 15;
    const int ty    = t >> 4;

    float acc[8][4] = {};

    #pragma unroll
    for (int c = 0; c < N_FEAT / LIN_KC; c++) {
        const int k0 = c * LIN_KC;

        for (int f = t; f < N_CLASSES * 16; f += 256) {
            int row = f >> 4, c4 = (f & 15) << 2;
            float4 v = reinterpret_cast<const float4*>(W + (size_t)row * N_FEAT + k0 + c4)[0];
            reinterpret_cast<float4*>(ws + row * LIN_PADC + c4)[0] = v;
        }
        for (int f = t; f < LIN_TM * 16; f += 256) {
            int row = f >> 4, c4 = (f & 15) << 2;
            int node = node0 + row;
            float4 v = (node < n)
                ? reinterpret_cast<const float4*>(x + (size_t)node * N_FEAT + k0 + c4)[0]
                : make_float4(0.f, 0.f, 0.f, 0.f);
            reinterpret_cast<float4*>(xs + row * LIN_PADC + c4)[0] = v;
        }
        __syncthreads();

        const float* xb = xs + (8 * ty) * LIN_PADC;
        #pragma unroll
        for (int k4 = 0; k4 < LIN_KC / 4; k4++) {
            float4 b[4];
            #pragma unroll
            for (int j = 0; j < 4; j++)
                b[j] = reinterpret_cast<const float4*>(ws + (tx + 16 * j) * LIN_PADC)[k4];
            #pragma unroll
            for (int i = 0; i < 8; i++) {
                float4 a = reinterpret_cast<const float4*>(xb + i * LIN_PADC)[k4];
                #pragma unroll
                for (int j = 0; j < 4; j++) {
                    acc[i][j] = fmaf(a.x, b[j].x, acc[i][j]);
                    acc[i][j] = fmaf(a.y, b[j].y, acc[i][j]);
                    acc[i][j] = fmaf(a.z, b[j].z, acc[i][j]);
                    acc[i][j] = fmaf(a.w, b[j].w, acc[i][j]);
                }
            }
        }
        __syncthreads();
    }

    #pragma unroll
    for (int i = 0; i < 8; i++) {
        int node = node0 + 8 * ty + i;
        if (node < n) {
            __half* o = g_y + (size_t)node * N_CLASSES + tx;
            o[0]  = __float2half_rn(acc[i][0]);
            o[16] = __float2half_rn(acc[i][1]);
            o[32] = __float2half_rn(acc[i][2]);
            o[48] = __float2half_rn(acc[i][3]);
        }
    }
}

// 5) scan apply: rowstart, fill cursor, dinv
__global__ void k_scan_apply(int n) {
    __shared__ int wsum[32];
    __shared__ int sexcl[SCAN_NB];
    const int lane = threadIdx.x & 31;
    const int wid  = threadIdx.x >> 5;

    if (wid == 0) {
        int i0 = 2 * lane, i1 = 2 * lane + 1;
        int a = (i0 < SCAN_NB) ? g_part[i0] : 0;
        int b = (i1 < SCAN_NB) ? g_part[i1] : 0;
        int pair = a + b, incl = pair;
        #pragma unroll
        for (int o = 1; o < 32; o <<= 1) {
            int tt = __shfl_up_sync(0xffffffffu, incl, o);
            if (lane >= o) incl += tt;
        }
        int excl = incl - pair;
        if (i0 < SCAN_NB) sexcl[i0] = excl;
        if (i1 < SCAN_NB) sexcl[i1] = excl + a;
    }
    __syncthreads();
    const int block_off = sexcl[blockIdx.x];

    int idx = blockIdx.x * SCAN_BLK + threadIdx.x;
    int v = (idx < n) ? g_cnt[idx] : 0;

    int incl = v;
    #pragma unroll
    for (int o = 1; o < 32; o <<= 1) {
        int t = __shfl_up_sync(0xffffffffu, incl, o);
        if (lane >= o) incl += t;
    }
    if (lane == 31) wsum[wid] = incl;
    __syncthreads();
    if (wid == 0) {
        int w = wsum[lane];
        int wi = w;
        #pragma unroll
        for (int o = 1; o < 32; o <<= 1) {
            int t = __shfl_up_sync(0xffffffffu, wi, o);
            if (lane >= o) wi += t;
        }
        wsum[lane] = wi - w;
    }
    __syncthreads();

    if (idx < n) {
        int excl = block_off + wsum[wid] + incl - v;
        g_rowstart[idx] = excl;
        g_fill[idx]     = excl;
        g_dinv[idx]     = rsqrtf((float)(v + 1));
    }
}

// 6) fill CSR columns
__global__ void k_fill(const int* __restrict__ buf, int E, int N) {
    int e = blockIdx.x * blockDim.x + threadIdx.x;
    if (e >= E) return;
    int s, d;
    if (g_is64) { s = buf[2 * e];  d = buf[2 * E + 2 * e]; }
    else        { s = buf[e];      d = buf[E + e]; }
    if ((unsigned)s >= (unsigned)N) s = 0;
    if ((unsigned)d >= (unsigned)N) d = 0;
    int pos = atomicAdd(&g_fill[d], 1);
    g_col[pos] = s;
}

// ---------------------------------------------------------------------------
// 7) scale y in place: ys = dinv * y. One thread per 8 halves (16B).
// ---------------------------------------------------------------------------
__global__ void k_scale(int n) {
    int v = blockIdx.x * blockDim.x + threadIdx.x;
    int total = n * (N_CLASSES / 8);
    if (v >= total) return;
    int row = v >> 3;                       // 8 chunks of 8 halves per row
    float di = g_dinv[row];
    float4 raw = reinterpret_cast<float4*>(g_y)[v];
    __half2* h = reinterpret_cast<__half2*>(&raw);
    #pragma unroll
    for (int q = 0; q < 4; q++) {
        float2 f = __half22float2(h[q]);
        h[q] = __floats2half2_rn(di * f.x, di * f.y);
    }
    reinterpret_cast<float4*>(g_y)[v] = raw;
}

// ---------------------------------------------------------------------------
// Hop core on pre-scaled rows: s = sum_j ys_j + ys_i. 2 LDG/edge (col + row).
// ---------------------------------------------------------------------------
__device__ __forceinline__ float2 hop_sum(const __half* __restrict__ yin,
                                          int i, int lane, int rs, int re) {
    float ax = 0.0f, ay = 0.0f;
    int e = rs;
    for (; e + 8 <= re; e += 8) {
        int     j[8];
        __half2 h[8];
        #pragma unroll
        for (int q = 0; q < 8; q++) j[q] = g_col[e + q];
        #pragma unroll
        for (int q = 0; q < 8; q++)
            h[q] = reinterpret_cast<const __half2*>(yin + (size_t)j[q] * N_CLASSES)[lane];
        #pragma unroll
        for (int q = 0; q < 8; q++) {
            float2 v = __half22float2(h[q]);
            ax += v.x; ay += v.y;
        }
    }
    for (; e < re; e++) {
        int jj = g_col[e];
        float2 v = __half22float2(
            reinterpret_cast<const __half2*>(yin + (size_t)jj * N_CLASSES)[lane]);
        ax += v.x; ay += v.y;
    }
    float2 self = __half22float2(
        reinterpret_cast<const __half2*>(yin + (size_t)i * N_CLASSES)[lane]);
    return make_float2(ax + self.x, ay + self.y);
}

// 8) hop 1: h1s = di^2 * (sum_j ys_j + ys_i)   [= di * hop1_ref]
__global__ void k_hop1() {
    int warp = (blockIdx.x * blockDim.x + threadIdx.x) >> 5;
    int lane = threadIdx.x & 31;
    if (warp >= N_NODES) return;
    const float di = g_dinv[warp];
    const int rs = g_rowstart[warp];
    const int re = rs + g_cnt[warp];
    float2 s = hop_sum(g_y, warp, lane, rs, re);
    float d2 = di * di;
    reinterpret_cast<__half2*>(g_h1 + (size_t)warp * N_CLASSES)[lane] =
        __floats2half2_rn(d2 * s.x, d2 * s.y);
}

// 9) hop 2 + bias + log_softmax: logits = di*(sum_j h1s_j + h1s_i) + b
__global__ void k_hop2_head(const float* __restrict__ b, float* __restrict__ out) {
    int warp = (blockIdx.x * blockDim.x + threadIdx.x) >> 5;
    int lane = threadIdx.x & 31;
    if (warp >= N_NODES) return;
    const float di = g_dinv[warp];
    const int rs = g_rowstart[warp];
    const int re = rs + g_cnt[warp];

    float2 s  = hop_sum(g_h1, warp, lane, rs, re);
    float2 bb = reinterpret_cast<const float2*>(b)[lane];
    float2 o;
    o.x = fmaf(di, s.x, bb.x);
    o.y = fmaf(di, s.y, bb.y);

    float m = fmaxf(o.x, o.y);
    #pragma unroll
    for (int q = 16; q; q >>= 1) m = fmaxf(m, __shfl_xor_sync(0xffffffffu, m, q));

    float ssum = __expf(o.x - m) + __expf(o.y - m);
    #pragma unroll
    for (int q = 16; q; q >>= 1) ssum += __shfl_xor_sync(0xffffffffu, ssum, q);

    float ls = m + __logf(ssum);
    float2 r;
    r.x = o.x - ls;
    r.y = o.y - ls;
    reinterpret_cast<float2*>(out + (size_t)warp * N_CLASSES)[lane] = r;
}

// ---------------------------------------------------------------------------
// launch: edge chain on capture stream; k_lin forked onto side stream.
// ---------------------------------------------------------------------------
extern "C" void kernel_launch(void* const* d_in, const int* in_sizes, int n_in,
                              void* d_out, int out_size) {
    int ix = 0, ie = 1, iw = 2, ib = 3;
    for (int k = 0; k < n_in && k < 4; k++) {
        if      (in_sizes[k] == N_NODES * N_FEAT)   ix = k;
        else if (in_sizes[k] == 2 * N_EDGES)        ie = k;
        else if (in_sizes[k] == N_CLASSES * N_FEAT) iw = k;
        else if (in_sizes[k] == N_CLASSES)          ib = k;
    }
    const float* x    = (const float*)d_in[ix];
    const int*   ebuf = (const int*)d_in[ie];
    const float* W    = (const float*)d_in[iw];
    const float* b    = (const float*)d_in[ib];
    float* out = (float*)d_out;

    const int N = N_NODES;
    const int E = N_EDGES;

    static int inited = 0;
    static cudaStream_t s1;
    static cudaEvent_t ev_fork, ev_join;
    if (!inited) {
        cudaFuncSetAttribute(k_lin, cudaFuncAttributeMaxDynamicSharedMemorySize, LIN_SMEM);
        cudaStreamCreateWithFlags(&s1, cudaStreamNonBlocking);
        cudaEventCreateWithFlags(&ev_fork, cudaEventDisableTiming);
        cudaEventCreateWithFlags(&ev_join, cudaEventDisableTiming);
        inited = 1;
    }

    // fork: GEMM overlaps the CSR build
    cudaEventRecord(ev_fork, 0);
    cudaStreamWaitEvent(s1, ev_fork, 0);
    k_lin<<<(N + LIN_TM - 1) / LIN_TM, 256, LIN_SMEM, s1>>>(x, W, N);
    cudaEventRecord(ev_join, s1);

    // edge chain
    k_init         <<<(N + 255) / 256, 256>>>(ebuf, N);
    k_count        <<<(E + 255) / 256, 256>>>(ebuf, E, N);
    k_scan_partials<<<SCAN_NB, SCAN_BLK>>>(N);
    k_scan_apply   <<<SCAN_NB, SCAN_BLK>>>(N);
    k_fill         <<<(E + 255) / 256, 256>>>(ebuf, E, N);

    // join: need both CSR/dinv and y
    cudaStreamWaitEvent(0, ev_join, 0);

    // ys = dinv * y (in place), then two 2-LDG/edge hops
    const int scale_total = N * (N_CLASSES / 8);
    k_scale<<<(scale_total + 255) / 256, 256>>>(N);

    const long long hop_threads = (long long)N * 32;
    const int hop_blocks = (int)((hop_threads + 255) / 256);
    k_hop1     <<<hop_blocks, 256>>>();
    k_hop2_head<<<hop_blocks, 256>>>(b, out);
}